// round 1
// baseline (speedup 1.0000x reference)
#include <cuda_runtime.h>
#include <math.h>
#include <stdint.h>

#define BB 4
#define SS 1024
#define DD 1536
#define DD2 3072
#define DH 768
#define NHEAD 12
#define HD 128
#define SM1 1023
#define MAXC 256

// ---------------- scratch (static device globals; no allocations) ----------------
__device__ float g_xling[(size_t)BB*SS*DD];
__device__ float g_norm[BB*SS];
__device__ float g_d1[BB*SS];
__device__ float g_d2[BB*SS];
__device__ float g_d4[BB*SS];
__device__ float g_base[BB*SM1];
__device__ float g_learned[BB*SM1];
__device__ float g_bi[(size_t)BB*SM1*DD2];
__device__ float g_h1[(size_t)BB*SM1*DD];
__device__ float g_h2[(size_t)BB*SM1*DH];
__device__ int   g_segstart[BB*(SS+1)];
__device__ int   g_nseg[BB];
__device__ int   g_qstart[BB*SS];
__device__ int   g_qend[BB*SS];
__device__ float g_qkv[(size_t)BB*SS*3*DD];
__device__ float g_ctx[(size_t)BB*SS*DD];
__device__ float g_ao[(size_t)BB*SS*DD];
__device__ float g_chunk[(size_t)BB*MAXC*DD];
__device__ float g_hb[(size_t)BB*MAXC*DD2];

__device__ __forceinline__ float gelu_f(float v){
    return 0.5f*v*(1.0f+erff(v*0.7071067811865476f));
}

// ---------------- generic SGEMM: C[m,n] = act(sum_k A[m,k]*W[n,k] + bias[n]) ----------------
// A: MxK row-major. W: NxK row-major (we compute A @ W^T). N,K multiples of 128/16; M guarded.
template<int ACT>
__global__ __launch_bounds__(256,2) void sgemm_kernel(
    const float* __restrict__ A, const float* __restrict__ W,
    const float* __restrict__ bias, float* __restrict__ C,
    int M, int N, int K)
{
    __shared__ float As[16][128];
    __shared__ float Ws[16][128];
    const int tid = threadIdx.x;
    const int bm = blockIdx.y*128, bn = blockIdx.x*128;
    const int tx = tid & 15, ty = tid >> 4;
    float acc[8][8];
    #pragma unroll
    for (int i=0;i<8;i++)
        #pragma unroll
        for (int j=0;j<8;j++) acc[i][j]=0.f;

    for (int k0=0;k0<K;k0+=16){
        #pragma unroll
        for (int i=0;i<2;i++){
            int id = tid + i*256;
            int row = id >> 2, c4 = (id & 3)*4;
            int grow = bm + row;
            float4 av = make_float4(0.f,0.f,0.f,0.f);
            if (grow < M) av = *(const float4*)(A + (size_t)grow*K + k0 + c4);
            As[c4+0][row]=av.x; As[c4+1][row]=av.y; As[c4+2][row]=av.z; As[c4+3][row]=av.w;
            float4 wv = *(const float4*)(W + (size_t)(bn+row)*K + k0 + c4);
            Ws[c4+0][row]=wv.x; Ws[c4+1][row]=wv.y; Ws[c4+2][row]=wv.z; Ws[c4+3][row]=wv.w;
        }
        __syncthreads();
        #pragma unroll
        for (int k=0;k<16;k++){
            float4 a0 = *(const float4*)&As[k][ty*4];
            float4 a1 = *(const float4*)&As[k][64+ty*4];
            float4 w0 = *(const float4*)&Ws[k][tx*4];
            float4 w1 = *(const float4*)&Ws[k][64+tx*4];
            float aa[8]={a0.x,a0.y,a0.z,a0.w,a1.x,a1.y,a1.z,a1.w};
            float ww[8]={w0.x,w0.y,w0.z,w0.w,w1.x,w1.y,w1.z,w1.w};
            #pragma unroll
            for (int i=0;i<8;i++)
                #pragma unroll
                for (int j=0;j<8;j++) acc[i][j] += aa[i]*ww[j];
        }
        __syncthreads();
    }
    float4 bz0 = *(const float4*)(bias + bn + tx*4);
    float4 bz1 = *(const float4*)(bias + bn + 64 + tx*4);
    float bcol[8]={bz0.x,bz0.y,bz0.z,bz0.w,bz1.x,bz1.y,bz1.z,bz1.w};
    #pragma unroll
    for (int i=0;i<8;i++){
        int grow = bm + ((i<4) ? (ty*4+i) : (64+ty*4+(i-4)));
        if (grow >= M) continue;
        float outv[8];
        #pragma unroll
        for (int j=0;j<8;j++){
            float v = acc[i][j] + bcol[j];
            if (ACT==1) v = gelu_f(v);
            outv[j]=v;
        }
        float* cp = C + (size_t)grow*N + bn;
        *(float4*)(cp + tx*4)      = make_float4(outv[0],outv[1],outv[2],outv[3]);
        *(float4*)(cp + 64 + tx*4) = make_float4(outv[4],outv[5],outv[6],outv[7]);
    }
}

// ---------------- row norms + strided dot products of x_ling ----------------
__global__ void normdot_kernel(){
    int s = blockIdx.x, b = blockIdx.y, t = threadIdx.x;
    const float* r0 = g_xling + ((size_t)(b*SS+s))*DD;
    float nn=0.f,p1=0.f,p2=0.f,p4=0.f;
    bool e1 = (s+1<SS), e2=(s+2<SS), e4=(s+4<SS);
    for (int i=t;i<DD;i+=256){
        float a=r0[i];
        nn += a*a;
        if (e1) p1 += a*r0[DD+i];
        if (e2) p2 += a*r0[2*DD+i];
        if (e4) p4 += a*r0[4*DD+i];
    }
    __shared__ float sh[256];
    sh[t]=nn; __syncthreads();
    for(int o=128;o>0;o>>=1){ if(t<o) sh[t]+=sh[t+o]; __syncthreads(); }
    if(t==0) g_norm[b*SS+s]=sqrtf(sh[0]);
    __syncthreads();
    sh[t]=p1; __syncthreads();
    for(int o=128;o>0;o>>=1){ if(t<o) sh[t]+=sh[t+o]; __syncthreads(); }
    if(t==0) g_d1[b*SS+s]=sh[0];
    __syncthreads();
    sh[t]=p2; __syncthreads();
    for(int o=128;o>0;o>>=1){ if(t<o) sh[t]+=sh[t+o]; __syncthreads(); }
    if(t==0) g_d2[b*SS+s]=sh[0];
    __syncthreads();
    sh[t]=p4; __syncthreads();
    for(int o=128;o>0;o>>=1){ if(t<o) sh[t]+=sh[t+o]; __syncthreads(); }
    if(t==0) g_d4[b*SS+s]=sh[0];
}

__device__ __forceinline__ float cosv(const float* nm, const float* dd, int s, int off){
    float na = fmaxf(nm[s],1e-8f), nb = fmaxf(nm[s+off],1e-8f);
    return dd[s]/(na*nb);
}

// ---------------- base = 0.5*(1 - mean of 3 interpolated cosine series) ----------------
__global__ void base_kernel(){
    int idx = blockIdx.x*256+threadIdx.x;
    if (idx >= BB*SM1) return;
    int b = idx / SM1, t = idx % SM1;
    const float* nm = g_norm + b*SS;
    float c1 = cosv(nm, g_d1 + b*SS, t, 1);
    // scale 2: L_in = 511
    const float r2 = (float)(511.0/1023.0);
    float src2 = fminf(fmaxf((t+0.5f)*r2 - 0.5f, 0.f), 510.f);
    int i0 = (int)floorf(src2); int i1 = min(i0+1,510); float w2 = src2 - (float)i0;
    float c2 = cosv(nm, g_d2 + b*SS, 2*i0, 2)*(1.f-w2) + cosv(nm, g_d2 + b*SS, 2*i1, 2)*w2;
    // scale 4: L_in = 255
    const float r4 = (float)(255.0/1023.0);
    float src4 = fminf(fmaxf((t+0.5f)*r4 - 0.5f, 0.f), 254.f);
    int j0=(int)floorf(src4); int j1=min(j0+1,254); float w4=src4-(float)j0;
    float c4 = cosv(nm, g_d4 + b*SS, 4*j0, 4)*(1.f-w4) + cosv(nm, g_d4 + b*SS, 4*j1, 4)*w4;
    float avg = (c1+c2+c4)/3.0f;
    g_base[idx] = 0.5f*(1.0f-avg);
}

// ---------------- bi = concat(x[:, :-1], x[:, 1:]) ----------------
__global__ void bi_kernel(const float* __restrict__ x){
    size_t i4 = (size_t)blockIdx.x*256+threadIdx.x;
    if (i4 >= (size_t)BB*SM1*DD2/4) return;
    size_t row = i4 / (DD2/4);
    int k = (int)(i4 % (DD2/4))*4;
    int b = (int)(row / SM1), s = (int)(row % SM1);
    const float* src = (k < DD) ? (x + ((size_t)(b*SS+s))*DD + k)
                                : (x + ((size_t)(b*SS+s+1))*DD + (k-DD));
    *(float4*)(g_bi + row*DD2 + k) = *(const float4*)src;
}

// ---------------- learned head: sigmoid(h2 . w3 + b3), accumulated over n ----------------
__global__ void det3_kernel(const float* __restrict__ w3, const float* __restrict__ b3, int accum){
    int gw = (blockIdx.x*256+threadIdx.x)>>5;
    int lane = threadIdx.x&31;
    if (gw >= BB*SM1) return;
    const float* r = g_h2 + (size_t)gw*DH;
    float d=0.f;
    for (int i=lane;i<DH;i+=32) d += r[i]*w3[i];
    #pragma unroll
    for (int o=16;o>0;o>>=1) d += __shfl_xor_sync(0xffffffffu,d,o);
    if (lane==0){
        float sg = 1.f/(1.f+expf(-(d+b3[0])));
        if (accum) g_learned[gw]+=sg; else g_learned[gw]=sg;
    }
}

// ---------------- boundaries -> segment ids -> per-query [start,end) ----------------
__global__ void seg_kernel(){
    int b = blockIdx.x, t = threadIdx.x;
    __shared__ int sh[SS];
    __shared__ int shns;
    int flag;
    if (t==0) flag=1;
    else {
        float fin = 0.6f*g_base[b*SM1 + (t-1)] + 0.4f*(g_learned[b*SM1 + (t-1)]/3.0f);
        flag = (fin > 0.5f) ? 1 : 0;
    }
    sh[t]=flag; __syncthreads();
    for (int o=1;o<SS;o<<=1){
        int add = (t>=o)? sh[t-o] : 0;
        __syncthreads();
        sh[t]+=add;
        __syncthreads();
    }
    int seg_t = sh[t]-1;
    if (flag) g_segstart[b*(SS+1)+seg_t]=t;
    if (t==SS-1){ g_nseg[b]=sh[t]; shns=sh[t]; }
    __syncthreads();
    int ns = shns;
    int st = g_segstart[b*(SS+1)+seg_t];
    int en = (seg_t+1<ns)? g_segstart[b*(SS+1)+seg_t+1] : SS;
    g_qstart[b*SS+t]=st; g_qend[b*SS+t]=en;
}

// ---------------- segmented attention: one warp per (b,q,h), online softmax ----------------
__global__ void attn_kernel(){
    int gw = (blockIdx.x*256 + threadIdx.x)>>5;
    int lane = threadIdx.x & 31;
    int b = gw / (SS*NHEAD);
    int rr = gw % (SS*NHEAD);
    int q = rr / NHEAD;
    int h = rr % NHEAD;
    const float* rowbase = g_qkv + (size_t)b*SS*3*DD;
    int off = h*HD + lane*4;
    float4 qv = *(const float4*)(rowbase + (size_t)q*3*DD + off);
    int s0 = g_qstart[b*SS+q], s1 = g_qend[b*SS+q];
    float m=-3.4e38f, l=0.f;
    float ax=0.f,ay=0.f,az=0.f,aw=0.f;
    for (int kk=s0; kk<s1; kk++){
        const float* kr = rowbase + (size_t)kk*3*DD;
        float4 kv = *(const float4*)(kr + DD + off);
        float d = qv.x*kv.x + qv.y*kv.y + qv.z*kv.z + qv.w*kv.w;
        #pragma unroll
        for (int o=16;o>0;o>>=1) d += __shfl_xor_sync(0xffffffffu,d,o);
        d = d / 11.313708498984761f;
        float mn = fmaxf(m,d);
        float f = expf(m-mn);
        float p = expf(d-mn);
        float4 vv = *(const float4*)(kr + 2*DD + off);
        ax=ax*f+p*vv.x; ay=ay*f+p*vv.y; az=az*f+p*vv.z; aw=aw*f+p*vv.w;
        l = l*f + p;
        m = mn;
    }
    float inv = 1.f/l;
    *(float4*)(g_ctx + ((size_t)(b*SS+q))*DD + off) = make_float4(ax*inv,ay*inv,az*inv,aw*inv);
}

// ---------------- per-chunk mean + size embedding + positional encoding ----------------
__global__ void chunk_kernel(const float* __restrict__ size_emb, const float* __restrict__ pos_enc){
    int m = blockIdx.x, b = blockIdx.y, t = threadIdx.x;
    int ns = g_nseg[b];
    int count=0, s0=0;
    if (m < ns){
        s0 = g_segstart[b*(SS+1)+m];
        int s1 = (m+1<ns)? g_segstart[b*(SS+1)+m+1] : SS;
        count = s1-s0;
    }
    int clen = min(count, 1023);
    for (int d=t; d<DD; d+=256){
        float v = 0.f;
        if (count>0){
            float s=0.f;
            const float* ap = g_ao + ((size_t)(b*SS+s0))*DD + d;
            for (int i=0;i<count;i++) s += ap[(size_t)i*DD];
            v = s/(float)count + size_emb[(size_t)clen*DD + d];
        }
        v += pos_enc[(size_t)m*DD + d];
        g_chunk[((size_t)(b*MAXC+m))*DD + d] = v;
    }
}

// ---------------- layernorm (in-place on output) ----------------
__global__ void ln_kernel(float* __restrict__ y, const float* __restrict__ g, const float* __restrict__ bt){
    int row = blockIdx.x; int t = threadIdx.x;
    float* r = y + (size_t)row*DD;
    __shared__ float sh[256];
    float s=0.f;
    for (int i=t;i<DD;i+=256) s += r[i];
    sh[t]=s; __syncthreads();
    for (int o=128;o>0;o>>=1){ if(t<o) sh[t]+=sh[t+o]; __syncthreads(); }
    float mu = sh[0]/(float)DD; __syncthreads();
    float v=0.f;
    for (int i=t;i<DD;i+=256){ float d=r[i]-mu; v+=d*d; }
    sh[t]=v; __syncthreads();
    for (int o=128;o>0;o>>=1){ if(t<o) sh[t]+=sh[t+o]; __syncthreads(); }
    float var = sh[0]/(float)DD;
    float inv = 1.f/sqrtf(var+1e-5f);
    for (int i=t;i<DD;i+=256) r[i] = (r[i]-mu)*inv*g[i]+bt[i];
}

// ---------------- host driver ----------------
static float* symf(const void* sym){
    void* p=nullptr;
    cudaGetSymbolAddress(&p, sym);
    return (float*)p;
}

extern "C" void kernel_launch(void* const* d_in, const int* in_sizes, int n_in,
                              void* d_out, int out_size){
    const float* x         = (const float*)d_in[0];
    const float* Wp        = (const float*)d_in[1];
    const float* bp        = (const float*)d_in[2];
    const float* detW1     = (const float*)d_in[3];
    const float* detb1     = (const float*)d_in[4];
    const float* detW2     = (const float*)d_in[5];
    const float* detb2     = (const float*)d_in[6];
    const float* detW3     = (const float*)d_in[7];
    const float* detb3     = (const float*)d_in[8];
    const float* in_proj_w = (const float*)d_in[9];
    const float* in_proj_b = (const float*)d_in[10];
    const float* out_w     = (const float*)d_in[11];
    const float* out_b     = (const float*)d_in[12];
    const float* size_emb  = (const float*)d_in[13];
    const float* pos_enc   = (const float*)d_in[14];
    const float* procW1    = (const float*)d_in[15];
    const float* procb1    = (const float*)d_in[16];
    const float* procW2    = (const float*)d_in[17];
    const float* procb2    = (const float*)d_in[18];
    const float* ln_g      = (const float*)d_in[19];
    const float* ln_b      = (const float*)d_in[20];
    float* outp = (float*)d_out;

    float* xling = symf(g_xling);
    float* bi    = symf(g_bi);
    float* h1    = symf(g_h1);
    float* h2    = symf(g_h2);
    float* qkv   = symf(g_qkv);
    float* ctx   = symf(g_ctx);
    float* ao    = symf(g_ao);
    float* chunk = symf(g_chunk);
    float* hb    = symf(g_hb);

    // 1) x_ling = x @ Wp^T + bp    (boundary-sensitive: fp32)
    sgemm_kernel<0><<<dim3(DD/128,(BB*SS+127)/128),256>>>(x, Wp, bp, xling, BB*SS, DD, DD);
    // 2) norms + strided dots, then base scores
    normdot_kernel<<<dim3(SS,BB),256>>>();
    base_kernel<<<(BB*SM1+255)/256,256>>>();
    // 3) detector MLPs (boundary-sensitive: fp32)
    bi_kernel<<<(int)(((size_t)BB*SM1*DD2/4 + 255)/256),256>>>(x);
    for (int n=0;n<3;n++){
        sgemm_kernel<1><<<dim3(DD/128,(BB*SM1+127)/128),256>>>(
            bi, detW1+(size_t)n*DD*DD2, detb1+(size_t)n*DD, h1, BB*SM1, DD, DD2);
        sgemm_kernel<1><<<dim3(DH/128,(BB*SM1+127)/128),256>>>(
            h1, detW2+(size_t)n*DH*DD, detb2+(size_t)n*DH, h2, BB*SM1, DH, DD);
        det3_kernel<<<(BB*SM1+7)/8,256>>>(detW3+(size_t)n*DH, detb3+n, n);
    }
    // 4) segmentation
    seg_kernel<<<BB,SS>>>();
    // 5) qkv projection
    sgemm_kernel<0><<<dim3(3*DD/128,(BB*SS+127)/128),256>>>(x, in_proj_w, in_proj_b, qkv, BB*SS, 3*DD, DD);
    // 6) segment-local attention
    attn_kernel<<<BB*SS*NHEAD/8,256>>>();
    // 7) output projection
    sgemm_kernel<0><<<dim3(DD/128,(BB*SS+127)/128),256>>>(ctx, out_w, out_b, ao, BB*SS, DD, DD);
    // 8) chunk pooling + size emb + pos enc
    chunk_kernel<<<dim3(MAXC,BB),256>>>(size_emb, pos_enc);
    // 9) chunk MLP
    sgemm_kernel<1><<<dim3(DD2/128,(BB*MAXC+127)/128),256>>>(chunk, procW1, procb1, hb, BB*MAXC, DD2, DD);
    sgemm_kernel<0><<<dim3(DD/128,(BB*MAXC+127)/128),256>>>(hb, procW2, procb2, outp, BB*MAXC, DD, DD2);
    // 10) layernorm in-place on output
    ln_kernel<<<BB*MAXC,256>>>(outp, ln_g, ln_b);
}

// round 3
// speedup vs baseline: 1.1444x; 1.1444x over previous
#include <cuda_runtime.h>
#include <math.h>
#include <stdint.h>

#define BB 4
#define SS 1024
#define DD 1536
#define DD2 3072
#define DH 768
#define NHEAD 12
#define HD 128
#define SM1 1023
#define MAXC 256

// ---------------- scratch (static device globals; no allocations) ----------------
__device__ float g_xling[(size_t)BB*SS*DD];
__device__ float g_norm[BB*SS];
__device__ float g_d1[BB*SS];
__device__ float g_d2[BB*SS];
__device__ float g_d4[BB*SS];
__device__ float g_base[BB*SM1];
__device__ float g_learned[BB*SM1];
__device__ float g_bi[(size_t)BB*SM1*DD2];
__device__ float g_h1[(size_t)BB*SM1*DD];
__device__ float g_h2[(size_t)BB*SM1*DH];
__device__ int   g_segstart[BB*(SS+1)];
__device__ int   g_nseg[BB];
__device__ int   g_qstart[BB*SS];
__device__ int   g_qend[BB*SS];
__device__ float g_qkv[(size_t)BB*SS*3*DD];
__device__ float g_ctx[(size_t)BB*SS*DD];
__device__ float g_ao[(size_t)BB*SS*DD];
__device__ float g_chunk[(size_t)BB*MAXC*DD];
__device__ float g_hb[(size_t)BB*MAXC*DD2];

__device__ __forceinline__ float gelu_f(float v){
    return 0.5f*v*(1.0f+erff(v*0.7071067811865476f));
}

// ---------------- SGEMM (double-buffered): C = act(A @ W^T + bias) ----------------
// A: MxK row-major. W: NxK row-major. N,K multiples of 128/16; M guarded.
// 128x128 block tile, 16-wide K tile, 8x8 per-thread microtile, 256 threads.
// Global loads for tile t+1 are issued before the compute on tile t (register
// prefetch), stores go to the alternate smem buffer, one __syncthreads per tile.
template<int ACT>
__global__ __launch_bounds__(256,2) void sgemm_kernel(
    const float* __restrict__ A, const float* __restrict__ W,
    const float* __restrict__ bias, float* __restrict__ C,
    int M, int N, int K)
{
    __shared__ float As[2][16][128];
    __shared__ float Ws[2][16][128];
    const int tid = threadIdx.x;
    const int bm = blockIdx.y*128, bn = blockIdx.x*128;
    const int tx = tid & 15, ty = tid >> 4;

    float acc[8][8];
    #pragma unroll
    for (int i=0;i<8;i++)
        #pragma unroll
        for (int j=0;j<8;j++) acc[i][j]=0.f;

    // per-thread load coords (covers all 128 rows x 16 cols with 2 iterations)
    const int r0 = tid>>2,           c0 = (tid&3)*4;        // id = tid
    const int r1 = (tid+256)>>2,     c1 = ((tid+256)&3)*4;  // id = tid+256

    float4 pa0, pa1, pw0, pw1;

    // prologue: global load tile 0
    {
        int g0 = bm + r0, g1 = bm + r1;
        pa0 = (g0 < M) ? *(const float4*)(A + (size_t)g0*K + c0) : make_float4(0.f,0.f,0.f,0.f);
        pa1 = (g1 < M) ? *(const float4*)(A + (size_t)g1*K + c1) : make_float4(0.f,0.f,0.f,0.f);
        pw0 = *(const float4*)(W + (size_t)(bn+r0)*K + c0);
        pw1 = *(const float4*)(W + (size_t)(bn+r1)*K + c1);
    }
    // store tile 0 -> buf 0 (transposed: smem is [k][m])
    As[0][c0+0][r0]=pa0.x; As[0][c0+1][r0]=pa0.y; As[0][c0+2][r0]=pa0.z; As[0][c0+3][r0]=pa0.w;
    As[0][c1+0][r1]=pa1.x; As[0][c1+1][r1]=pa1.y; As[0][c1+2][r1]=pa1.z; As[0][c1+3][r1]=pa1.w;
    Ws[0][c0+0][r0]=pw0.x; Ws[0][c0+1][r0]=pw0.y; Ws[0][c0+2][r0]=pw0.z; Ws[0][c0+3][r0]=pw0.w;
    Ws[0][c1+0][r1]=pw1.x; Ws[0][c1+1][r1]=pw1.y; Ws[0][c1+2][r1]=pw1.z; Ws[0][c1+3][r1]=pw1.w;
    __syncthreads();

    int buf = 0;
    for (int k0 = 16; k0 < K; k0 += 16){
        // prefetch next tile's globals into registers (in flight during compute)
        {
            int g0 = bm + r0, g1 = bm + r1;
            pa0 = (g0 < M) ? *(const float4*)(A + (size_t)g0*K + k0 + c0) : make_float4(0.f,0.f,0.f,0.f);
            pa1 = (g1 < M) ? *(const float4*)(A + (size_t)g1*K + k0 + c1) : make_float4(0.f,0.f,0.f,0.f);
            pw0 = *(const float4*)(W + (size_t)(bn+r0)*K + k0 + c0);
            pw1 = *(const float4*)(W + (size_t)(bn+r1)*K + k0 + c1);
        }
        // compute on current buffer
        #pragma unroll
        for (int k=0;k<16;k++){
            float4 a0 = *(const float4*)&As[buf][k][ty*4];
            float4 a1 = *(const float4*)&As[buf][k][64+ty*4];
            float4 w0 = *(const float4*)&Ws[buf][k][tx*4];
            float4 w1 = *(const float4*)&Ws[buf][k][64+tx*4];
            float aa[8]={a0.x,a0.y,a0.z,a0.w,a1.x,a1.y,a1.z,a1.w};
            float ww[8]={w0.x,w0.y,w0.z,w0.w,w1.x,w1.y,w1.z,w1.w};
            #pragma unroll
            for (int i=0;i<8;i++)
                #pragma unroll
                for (int j=0;j<8;j++) acc[i][j] += aa[i]*ww[j];
        }
        // stash prefetched tile into the other buffer (safe: last reads of that
        // buffer completed before the previous __syncthreads)
        int nb = buf ^ 1;
        As[nb][c0+0][r0]=pa0.x; As[nb][c0+1][r0]=pa0.y; As[nb][c0+2][r0]=pa0.z; As[nb][c0+3][r0]=pa0.w;
        As[nb][c1+0][r1]=pa1.x; As[nb][c1+1][r1]=pa1.y; As[nb][c1+2][r1]=pa1.z; As[nb][c1+3][r1]=pa1.w;
        Ws[nb][c0+0][r0]=pw0.x; Ws[nb][c0+1][r0]=pw0.y; Ws[nb][c0+2][r0]=pw0.z; Ws[nb][c0+3][r0]=pw0.w;
        Ws[nb][c1+0][r1]=pw1.x; Ws[nb][c1+1][r1]=pw1.y; Ws[nb][c1+2][r1]=pw1.z; Ws[nb][c1+3][r1]=pw1.w;
        __syncthreads();
        buf = nb;
    }
    // final tile
    #pragma unroll
    for (int k=0;k<16;k++){
        float4 a0 = *(const float4*)&As[buf][k][ty*4];
        float4 a1 = *(const float4*)&As[buf][k][64+ty*4];
        float4 w0 = *(const float4*)&Ws[buf][k][tx*4];
        float4 w1 = *(const float4*)&Ws[buf][k][64+tx*4];
        float aa[8]={a0.x,a0.y,a0.z,a0.w,a1.x,a1.y,a1.z,a1.w};
        float ww[8]={w0.x,w0.y,w0.z,w0.w,w1.x,w1.y,w1.z,w1.w};
        #pragma unroll
        for (int i=0;i<8;i++)
            #pragma unroll
            for (int j=0;j<8;j++) acc[i][j] += aa[i]*ww[j];
    }

    float4 bz0 = *(const float4*)(bias + bn + tx*4);
    float4 bz1 = *(const float4*)(bias + bn + 64 + tx*4);
    float bcol[8]={bz0.x,bz0.y,bz0.z,bz0.w,bz1.x,bz1.y,bz1.z,bz1.w};
    #pragma unroll
    for (int i=0;i<8;i++){
        int grow = bm + ((i<4) ? (ty*4+i) : (64+ty*4+(i-4)));
        if (grow >= M) continue;
        float outv[8];
        #pragma unroll
        for (int j=0;j<8;j++){
            float v = acc[i][j] + bcol[j];
            if (ACT==1) v = gelu_f(v);
            outv[j]=v;
        }
        float* cp = C + (size_t)grow*N + bn;
        *(float4*)(cp + tx*4)      = make_float4(outv[0],outv[1],outv[2],outv[3]);
        *(float4*)(cp + 64 + tx*4) = make_float4(outv[4],outv[5],outv[6],outv[7]);
    }
}

// ---------------- row norms + strided dot products of x_ling ----------------
__global__ void normdot_kernel(){
    int s = blockIdx.x, b = blockIdx.y, t = threadIdx.x;
    const float* r0 = g_xling + ((size_t)(b*SS+s))*DD;
    float nn=0.f,p1=0.f,p2=0.f,p4=0.f;
    bool e1 = (s+1<SS), e2=(s+2<SS), e4=(s+4<SS);
    for (int i=t;i<DD;i+=256){
        float a=r0[i];
        nn += a*a;
        if (e1) p1 += a*r0[DD+i];
        if (e2) p2 += a*r0[2*DD+i];
        if (e4) p4 += a*r0[4*DD+i];
    }
    __shared__ float sh[256];
    sh[t]=nn; __syncthreads();
    for(int o=128;o>0;o>>=1){ if(t<o) sh[t]+=sh[t+o]; __syncthreads(); }
    if(t==0) g_norm[b*SS+s]=sqrtf(sh[0]);
    __syncthreads();
    sh[t]=p1; __syncthreads();
    for(int o=128;o>0;o>>=1){ if(t<o) sh[t]+=sh[t+o]; __syncthreads(); }
    if(t==0) g_d1[b*SS+s]=sh[0];
    __syncthreads();
    sh[t]=p2; __syncthreads();
    for(int o=128;o>0;o>>=1){ if(t<o) sh[t]+=sh[t+o]; __syncthreads(); }
    if(t==0) g_d2[b*SS+s]=sh[0];
    __syncthreads();
    sh[t]=p4; __syncthreads();
    for(int o=128;o>0;o>>=1){ if(t<o) sh[t]+=sh[t+o]; __syncthreads(); }
    if(t==0) g_d4[b*SS+s]=sh[0];
}

__device__ __forceinline__ float cosv(const float* nm, const float* dd, int s, int off){
    float na = fmaxf(nm[s],1e-8f), nb = fmaxf(nm[s+off],1e-8f);
    return dd[s]/(na*nb);
}

// ---------------- base = 0.5*(1 - mean of 3 interpolated cosine series) ----------------
__global__ void base_kernel(){
    int idx = blockIdx.x*256+threadIdx.x;
    if (idx >= BB*SM1) return;
    int b = idx / SM1, t = idx % SM1;
    const float* nm = g_norm + b*SS;
    float c1 = cosv(nm, g_d1 + b*SS, t, 1);
    // scale 2: L_in = 511
    const float r2 = (float)(511.0/1023.0);
    float src2 = fminf(fmaxf((t+0.5f)*r2 - 0.5f, 0.f), 510.f);
    int i0 = (int)floorf(src2); int i1 = min(i0+1,510); float w2 = src2 - (float)i0;
    float c2 = cosv(nm, g_d2 + b*SS, 2*i0, 2)*(1.f-w2) + cosv(nm, g_d2 + b*SS, 2*i1, 2)*w2;
    // scale 4: L_in = 255
    const float r4 = (float)(255.0/1023.0);
    float src4 = fminf(fmaxf((t+0.5f)*r4 - 0.5f, 0.f), 254.f);
    int j0=(int)floorf(src4); int j1=min(j0+1,254); float w4=src4-(float)j0;
    float c4 = cosv(nm, g_d4 + b*SS, 4*j0, 4)*(1.f-w4) + cosv(nm, g_d4 + b*SS, 4*j1, 4)*w4;
    float avg = (c1+c2+c4)/3.0f;
    g_base[idx] = 0.5f*(1.0f-avg);
}

// ---------------- bi = concat(x[:, :-1], x[:, 1:]) ----------------
__global__ void bi_kernel(const float* __restrict__ x){
    size_t i4 = (size_t)blockIdx.x*256+threadIdx.x;
    if (i4 >= (size_t)BB*SM1*DD2/4) return;
    size_t row = i4 / (DD2/4);
    int k = (int)(i4 % (DD2/4))*4;
    int b = (int)(row / SM1), s = (int)(row % SM1);
    const float* src = (k < DD) ? (x + ((size_t)(b*SS+s))*DD + k)
                                : (x + ((size_t)(b*SS+s+1))*DD + (k-DD));
    *(float4*)(g_bi + row*DD2 + k) = *(const float4*)src;
}

// ---------------- learned head: sigmoid(h2 . w3 + b3), accumulated over n ----------------
__global__ void det3_kernel(const float* __restrict__ w3, const float* __restrict__ b3, int accum){
    int gw = (blockIdx.x*256+threadIdx.x)>>5;
    int lane = threadIdx.x&31;
    if (gw >= BB*SM1) return;
    const float* r = g_h2 + (size_t)gw*DH;
    float d=0.f;
    for (int i=lane;i<DH;i+=32) d += r[i]*w3[i];
    #pragma unroll
    for (int o=16;o>0;o>>=1) d += __shfl_xor_sync(0xffffffffu,d,o);
    if (lane==0){
        float sg = 1.f/(1.f+expf(-(d+b3[0])));
        if (accum) g_learned[gw]+=sg; else g_learned[gw]=sg;
    }
}

// ---------------- boundaries -> segment ids -> per-query [start,end) ----------------
__global__ void seg_kernel(){
    int b = blockIdx.x, t = threadIdx.x;
    __shared__ int sh[SS];
    __shared__ int shns;
    int flag;
    if (t==0) flag=1;
    else {
        float fin = 0.6f*g_base[b*SM1 + (t-1)] + 0.4f*(g_learned[b*SM1 + (t-1)]/3.0f);
        flag = (fin > 0.5f) ? 1 : 0;
    }
    sh[t]=flag; __syncthreads();
    for (int o=1;o<SS;o<<=1){
        int add = (t>=o)? sh[t-o] : 0;
        __syncthreads();
        sh[t]+=add;
        __syncthreads();
    }
    int seg_t = sh[t]-1;
    if (flag) g_segstart[b*(SS+1)+seg_t]=t;
    if (t==SS-1){ g_nseg[b]=sh[t]; shns=sh[t]; }
    __syncthreads();
    int ns = shns;
    int st = g_segstart[b*(SS+1)+seg_t];
    int en = (seg_t+1<ns)? g_segstart[b*(SS+1)+seg_t+1] : SS;
    g_qstart[b*SS+t]=st; g_qend[b*SS+t]=en;
}

// ---------------- segmented attention: one warp per (b,q,h), online softmax ----------------
__global__ void attn_kernel(){
    int gw = (blockIdx.x*256 + threadIdx.x)>>5;
    int lane = threadIdx.x & 31;
    int b = gw / (SS*NHEAD);
    int rr = gw % (SS*NHEAD);
    int q = rr / NHEAD;
    int h = rr % NHEAD;
    const float* rowbase = g_qkv + (size_t)b*SS*3*DD;
    int off = h*HD + lane*4;
    float4 qv = *(const float4*)(rowbase + (size_t)q*3*DD + off);
    int s0 = g_qstart[b*SS+q], s1 = g_qend[b*SS+q];
    float m=-3.4e38f, l=0.f;
    float ax=0.f,ay=0.f,az=0.f,aw=0.f;
    for (int kk=s0; kk<s1; kk++){
        const float* kr = rowbase + (size_t)kk*3*DD;
        float4 kv = *(const float4*)(kr + DD + off);
        float d = qv.x*kv.x + qv.y*kv.y + qv.z*kv.z + qv.w*kv.w;
        #pragma unroll
        for (int o=16;o>0;o>>=1) d += __shfl_xor_sync(0xffffffffu,d,o);
        d = d / 11.313708498984761f;
        float mn = fmaxf(m,d);
        float f = expf(m-mn);
        float p = expf(d-mn);
        float4 vv = *(const float4*)(kr + 2*DD + off);
        ax=ax*f+p*vv.x; ay=ay*f+p*vv.y; az=az*f+p*vv.z; aw=aw*f+p*vv.w;
        l = l*f + p;
        m = mn;
    }
    float inv = 1.f/l;
    *(float4*)(g_ctx + ((size_t)(b*SS+q))*DD + off) = make_float4(ax*inv,ay*inv,az*inv,aw*inv);
}

// ---------------- per-chunk mean + size embedding + positional encoding ----------------
__global__ void chunk_kernel(const float* __restrict__ size_emb, const float* __restrict__ pos_enc){
    int m = blockIdx.x, b = blockIdx.y, t = threadIdx.x;
    int ns = g_nseg[b];
    int count=0, s0=0;
    if (m < ns){
        s0 = g_segstart[b*(SS+1)+m];
        int s1 = (m+1<ns)? g_segstart[b*(SS+1)+m+1] : SS;
        count = s1-s0;
    }
    int clen = min(count, 1023);
    for (int d=t; d<DD; d+=256){
        float v = 0.f;
        if (count>0){
            float s=0.f;
            const float* ap = g_ao + ((size_t)(b*SS+s0))*DD + d;
            for (int i=0;i<count;i++) s += ap[(size_t)i*DD];
            v = s/(float)count + size_emb[(size_t)clen*DD + d];
        }
        v += pos_enc[(size_t)m*DD + d];
        g_chunk[((size_t)(b*MAXC+m))*DD + d] = v;
    }
}

// ---------------- layernorm (in-place on output) ----------------
__global__ void ln_kernel(float* __restrict__ y, const float* __restrict__ g, const float* __restrict__ bt){
    int row = blockIdx.x; int t = threadIdx.x;
    float* r = y + (size_t)row*DD;
    __shared__ float sh[256];
    float s=0.f;
    for (int i=t;i<DD;i+=256) s += r[i];
    sh[t]=s; __syncthreads();
    for (int o=128;o>0;o>>=1){ if(t<o) sh[t]+=sh[t+o]; __syncthreads(); }
    float mu = sh[0]/(float)DD; __syncthreads();
    float v=0.f;
    for (int i=t;i<DD;i+=256){ float d=r[i]-mu; v+=d*d; }
    sh[t]=v; __syncthreads();
    for (int o=128;o>0;o>>=1){ if(t<o) sh[t]+=sh[t+o]; __syncthreads(); }
    float var = sh[0]/(float)DD;
    float inv = 1.f/sqrtf(var+1e-5f);
    for (int i=t;i<DD;i+=256) r[i] = (r[i]-mu)*inv*g[i]+bt[i];
}

// ---------------- host driver ----------------
static float* symf(const void* sym){
    void* p=nullptr;
    cudaGetSymbolAddress(&p, sym);
    return (float*)p;
}

extern "C" void kernel_launch(void* const* d_in, const int* in_sizes, int n_in,
                              void* d_out, int out_size){
    const float* x         = (const float*)d_in[0];
    const float* Wp        = (const float*)d_in[1];
    const float* bp        = (const float*)d_in[2];
    const float* detW1     = (const float*)d_in[3];
    const float* detb1     = (const float*)d_in[4];
    const float* detW2     = (const float*)d_in[5];
    const float* detb2     = (const float*)d_in[6];
    const float* detW3     = (const float*)d_in[7];
    const float* detb3     = (const float*)d_in[8];
    const float* in_proj_w = (const float*)d_in[9];
    const float* in_proj_b = (const float*)d_in[10];
    const float* out_w     = (const float*)d_in[11];
    const float* out_b     = (const float*)d_in[12];
    const float* size_emb  = (const float*)d_in[13];
    const float* pos_enc   = (const float*)d_in[14];
    const float* procW1    = (const float*)d_in[15];
    const float* procb1    = (const float*)d_in[16];
    const float* procW2    = (const float*)d_in[17];
    const float* procb2    = (const float*)d_in[18];
    const float* ln_g      = (const float*)d_in[19];
    const float* ln_b      = (const float*)d_in[20];
    float* outp = (float*)d_out;

    float* xling = symf(g_xling);
    float* bi    = symf(g_bi);
    float* h1    = symf(g_h1);
    float* h2    = symf(g_h2);
    float* qkv   = symf(g_qkv);
    float* ctx   = symf(g_ctx);
    float* ao    = symf(g_ao);
    float* chunk = symf(g_chunk);
    float* hb    = symf(g_hb);

    // 1) x_ling = x @ Wp^T + bp    (boundary-sensitive: fp32)
    sgemm_kernel<0><<<dim3(DD/128,(BB*SS+127)/128),256>>>(x, Wp, bp, xling, BB*SS, DD, DD);
    // 2) norms + strided dots, then base scores
    normdot_kernel<<<dim3(SS,BB),256>>>();
    base_kernel<<<(BB*SM1+255)/256,256>>>();
    // 3) detector MLPs (boundary-sensitive: fp32)
    bi_kernel<<<(int)(((size_t)BB*SM1*DD2/4 + 255)/256),256>>>(x);
    for (int n=0;n<3;n++){
        sgemm_kernel<1><<<dim3(DD/128,(BB*SM1+127)/128),256>>>(
            bi, detW1+(size_t)n*DD*DD2, detb1+(size_t)n*DD, h1, BB*SM1, DD, DD2);
        sgemm_kernel<1><<<dim3(DH/128,(BB*SM1+127)/128),256>>>(
            h1, detW2+(size_t)n*DH*DD, detb2+(size_t)n*DH, h2, BB*SM1, DH, DD);
        det3_kernel<<<(BB*SM1+7)/8,256>>>(detW3+(size_t)n*DH, detb3+n, n);
    }
    // 4) segmentation
    seg_kernel<<<BB,SS>>>();
    // 5) qkv projection
    sgemm_kernel<0><<<dim3(3*DD/128,(BB*SS+127)/128),256>>>(x, in_proj_w, in_proj_b, qkv, BB*SS, 3*DD, DD);
    // 6) segment-local attention
    attn_kernel<<<BB*SS*NHEAD/8,256>>>();
    // 7) output projection
    sgemm_kernel<0><<<dim3(DD/128,(BB*SS+127)/128),256>>>(ctx, out_w, out_b, ao, BB*SS, DD, DD);
    // 8) chunk pooling + size emb + pos enc
    chunk_kernel<<<dim3(MAXC,BB),256>>>(size_emb, pos_enc);
    // 9) chunk MLP
    sgemm_kernel<1><<<dim3(DD2/128,(BB*MAXC+127)/128),256>>>(chunk, procW1, procb1, hb, BB*MAXC, DD2, DD);
    sgemm_kernel<0><<<dim3(DD/128,(BB*MAXC+127)/128),256>>>(hb, procW2, procb2, outp, BB*MAXC, DD, DD2);
    // 10) layernorm in-place on output
    ln_kernel<<<BB*MAXC,256>>>(outp, ln_g, ln_b);
}